// round 11
// baseline (speedup 1.0000x reference)
#include <cuda_runtime.h>
#include <cuda_bf16.h>
#include <math.h>

#define N_STATES 65536
#define BATCH 256

// Per-batch data computed by prep:
// g_B: sites 5..8 structured factors, 20 floats each: [b*80 + (q-5)*20 + i]
// g_T: tail dot matrix, 32 rows x 8:                   [b*256 + j*8 + k]
// g_U: bond vectors after sites 15..9:                 [((b*8+s)*16+v)*8 + k]
__device__ float g_B[BATCH * 80];
__device__ float g_T[BATCH * 256];
__device__ float g_U[BATCH * 8 * 16 * 8];

// ---------------------------------------------------------------------------
// Structured site tensor: 20 floats B = {B1[4], B2[8], B3[8]}.
// Forward matvec: uo[l1+2l2+4l3] = sum_{r1,r2} B1[l1,r1] B2[l2,r2,r1] B3[l3,x,r2]
//                                   * u[r1+2r2+4x]
// ---------------------------------------------------------------------------
__device__ __forceinline__ void site_mv(const float* __restrict__ B, int x,
                                        const float* __restrict__ u,
                                        float* __restrict__ uo) {
    const float* B2 = B + 4;
    const float* B3 = B + 12;
    float va[8];
    #pragma unroll
    for (int l3 = 0; l3 < 2; l3++)
        #pragma unroll
        for (int r2 = 0; r2 < 2; r2++) {
            float c = B3[l3 * 4 + x * 2 + r2];
            #pragma unroll
            for (int r1 = 0; r1 < 2; r1++)
                va[l3 * 4 + r2 * 2 + r1] = c * u[r1 + 2 * r2 + 4 * x];
        }
    float vb[8];
    #pragma unroll
    for (int l3 = 0; l3 < 2; l3++)
        #pragma unroll
        for (int l2 = 0; l2 < 2; l2++)
            #pragma unroll
            for (int r1 = 0; r1 < 2; r1++)
                vb[l3 * 4 + l2 * 2 + r1] =
                    fmaf(B2[l2 * 4 + 2 + r1], va[l3 * 4 + 2 + r1],
                         B2[l2 * 4 + 0 + r1] * va[l3 * 4 + 0 + r1]);
    #pragma unroll
    for (int l3 = 0; l3 < 2; l3++)
        #pragma unroll
        for (int l2 = 0; l2 < 2; l2++)
            #pragma unroll
            for (int l1 = 0; l1 < 2; l1++)
                uo[l1 + 2 * l2 + 4 * l3] =
                    fmaf(B[l1 * 2 + 1], vb[l3 * 4 + l2 * 2 + 1],
                         B[l1 * 2 + 0] * vb[l3 * 4 + l2 * 2 + 0]);
}

// Transposed apply (row vector): vo = v * P(x).  Output nonzero only at
// third-index == x (delta structure), matching the forward read pattern.
__device__ __forceinline__ void site_mv_T(const float* __restrict__ B, int x,
                                          const float* __restrict__ v,
                                          float* __restrict__ vo) {
    const float* B2 = B + 4;
    const float* B3 = B + 12;
    float w[8];   // [l3*4 + l2*2 + r1]
    #pragma unroll
    for (int l3 = 0; l3 < 2; l3++)
        #pragma unroll
        for (int l2 = 0; l2 < 2; l2++)
            #pragma unroll
            for (int r1 = 0; r1 < 2; r1++)
                w[l3 * 4 + l2 * 2 + r1] =
                    fmaf(v[1 + 2 * l2 + 4 * l3], B[2 + r1],
                         v[0 + 2 * l2 + 4 * l3] * B[0 + r1]);
    float w2[8];  // [l3*4 + r2*2 + r1]
    #pragma unroll
    for (int l3 = 0; l3 < 2; l3++)
        #pragma unroll
        for (int r2 = 0; r2 < 2; r2++)
            #pragma unroll
            for (int r1 = 0; r1 < 2; r1++)
                w2[l3 * 4 + r2 * 2 + r1] =
                    fmaf(B2[4 + r2 * 2 + r1], w[l3 * 4 + 2 + r1],
                         B2[0 + r2 * 2 + r1] * w[l3 * 4 + 0 + r1]);
    #pragma unroll
    for (int r2 = 0; r2 < 2; r2++)
        #pragma unroll
        for (int r1 = 0; r1 < 2; r1++) {
            vo[r1 + 2 * r2 + 4 * x] =
                fmaf(B3[4 + x * 2 + r2], w2[4 + r2 * 2 + r1],
                     B3[0 + x * 2 + r2] * w2[0 + r2 * 2 + r1]);
            vo[r1 + 2 * r2 + 4 * (1 - x)] = 0.0f;
        }
}

// B-factor builder: B^{l=0} = M ; B^{l=1}[i,j] = (1-p) M[i,j] + p M[1-i,j]
__device__ __forceinline__ float bgf(const float* M, float p, int l, int i, int j) {
    float v = M[i * 2 + j];
    if (l) v = (1.0f - p) * v + p * M[(1 - i) * 2 + j];
    return v;
}

// ---------------------------------------------------------------------------
// Prep (grid BATCH, 128 thr): MLP -> gates -> site factors -> U table, T matrix.
// ---------------------------------------------------------------------------
__global__ void prep_kernel(const float* __restrict__ X,
                            const float* __restrict__ rot,
                            const float* __restrict__ ent,
                            const float* __restrict__ W1,
                            const float* __restrict__ b1,
                            const float* __restrict__ W2,
                            const float* __restrict__ b2) {
    int b = blockIdx.x;
    int t = threadIdx.x;  // 128 threads
    __shared__ float sx[100];
    __shared__ float sh[64];
    __shared__ float shq[16];
    __shared__ float sM[3][16][4];
    __shared__ float sp[3][15];
    __shared__ float sB[13 * 20];   // sites 2..14: (q-2)*20
    __shared__ float sW15[16];      // w15[x*8 + (l1+2l2+4l3)]
    __shared__ float sr01[16];      // r01[(x1*2+x0)*4 + i]

    if (t < 100) sx[t] = X[b * 100 + t];
    __syncthreads();

    if (t < 64) {
        float acc = b1[t];
        #pragma unroll 4
        for (int k = 0; k < 100; k++) acc = fmaf(sx[k], W1[k * 64 + t], acc);
        sh[t] = fmaxf(acc, 0.0f);
    }
    __syncthreads();

    if (t < 16) {
        float acc = b2[t];
        #pragma unroll
        for (int j = 0; j < 64; j++) acc = fmaf(sh[j], W2[j * 16 + t], acc);
        shq[t] = tanhf(acc);
    }
    __syncthreads();

    if (t < 48) {
        int layer = t / 16, q = t % 16;
        float hv = shq[q];
        float c[3], s[3];
        #pragma unroll
        for (int i = 0; i < 3; i++) {
            float ang = rot[(layer * 16 + q) * 3 + i] * hv;
            sincosf(0.5f * ang, &s[i], &c[i]);
        }
        sM[layer][q][0] =  c[0] * c[1] * c[2];
        sM[layer][q][1] = -s[0] * s[1] * s[2];
        sM[layer][q][2] =  s[0] * s[1] * c[2];
        sM[layer][q][3] =  c[0] * c[1] * s[2];
    }
    if (t >= 48 && t < 93) {
        int i = t - 48;
        sp[i / 15][i % 15] = 1.0f / (1.0f + expf(-ent[i]));
    }
    __syncthreads();

    // --- site factors for q=2..14 ---
    if (t >= 2 && t <= 14) {
        int q = t;
        float* o = sB + (q - 2) * 20;
        float p1 = sp[0][q - 1], p2 = sp[1][q - 1], p3 = sp[2][q - 1];
        const float* M1 = sM[0][q];
        const float* M2 = sM[1][q];
        const float* M3 = sM[2][q];
        #pragma unroll
        for (int l = 0; l < 2; l++)
            #pragma unroll
            for (int r1 = 0; r1 < 2; r1++)
                o[l * 2 + r1] = bgf(M1, p1, l, r1, 0);
        #pragma unroll
        for (int l = 0; l < 2; l++)
            #pragma unroll
            for (int r2 = 0; r2 < 2; r2++)
                #pragma unroll
                for (int r1 = 0; r1 < 2; r1++)
                    o[4 + l * 4 + r2 * 2 + r1] = bgf(M2, p2, l, r2, r1);
        #pragma unroll
        for (int l = 0; l < 2; l++)
            #pragma unroll
            for (int x = 0; x < 2; x++)
                #pragma unroll
                for (int r2 = 0; r2 < 2; r2++)
                    o[12 + l * 4 + x * 2 + r2] = bgf(M3, p3, l, x, r2);
    }
    if (t == 15) {
        // w15[x][l1,l2,l3] = (B3_{l3} B2_{l2} B1_{l1})[x,0] at site 15
        float p1 = sp[0][14], p2 = sp[1][14], p3 = sp[2][14];
        const float* M1 = sM[0][15];
        const float* M2 = sM[1][15];
        const float* M3 = sM[2][15];
        for (int x = 0; x < 2; x++)
            for (int l3 = 0; l3 < 2; l3++)
                for (int l2 = 0; l2 < 2; l2++)
                    for (int l1 = 0; l1 < 2; l1++) {
                        float acc = 0.0f;
                        for (int i = 0; i < 2; i++)
                            for (int j = 0; j < 2; j++)
                                acc += bgf(M3, p3, l3, x, i) *
                                       bgf(M2, p2, l2, i, j) *
                                       bgf(M1, p1, l1, j, 0);
                        sW15[x * 8 + (l1 + 2 * l2 + 4 * l3)] = acc;
                    }
    }
    if (t == 16) {
        // r01[x0,x1][r1,r2]: sites 0+1 contracted
        float p1 = sp[0][0], p2 = sp[1][0], p3 = sp[2][0];
        const float* N1 = sM[0][0];
        const float* N2 = sM[1][0];
        const float* N3 = sM[2][0];
        const float* M1 = sM[0][1];
        const float* M2 = sM[1][1];
        const float* M3 = sM[2][1];
        for (int x1 = 0; x1 < 2; x1++)
            for (int x0 = 0; x0 < 2; x0++)
                for (int r2 = 0; r2 < 2; r2++)
                    for (int r1 = 0; r1 < 2; r1++) {
                        float acc = 0.0f;
                        for (int l1 = 0; l1 < 2; l1++)
                            for (int l2 = 0; l2 < 2; l2++)
                                acc += N1[l1 * 2] * N2[l2 * 2 + l1] * N3[x0 * 2 + l2]
                                     * bgf(M1, p1, l1, r1, 0)
                                     * bgf(M2, p2, l2, r2, r1)
                                     * bgf(M3, p3, x0, x1, r2);
                        sr01[(x1 * 2 + x0) * 4 + (r1 + 2 * r2)] = acc;
                    }
    }
    __syncthreads();

    // --- export site 5..8 factors ---
    if (t < 80) g_B[b * 80 + t] = sB[(5 - 2) * 20 + t];

    // --- U table: one (s,v) combo per thread ---
    {
        const int s = t >> 4, v = t & 15;
        float u[8], u2[8];
        const int x15 = (s >> 2) & 1;
        #pragma unroll
        for (int i = 0; i < 8; i++) u[i] = sW15[x15 * 8 + i];
        site_mv(sB + (14 - 2) * 20, (s >> 1) & 1, u, u2);
        site_mv(sB + (13 - 2) * 20, s & 1, u2, u);
        site_mv(sB + (12 - 2) * 20, (v >> 3) & 1, u, u2);
        site_mv(sB + (11 - 2) * 20, (v >> 2) & 1, u2, u);
        site_mv(sB + (10 - 2) * 20, (v >> 1) & 1, u, u2);
        site_mv(sB + (9 - 2) * 20, v & 1, u2, u);
        float* dst = g_U + ((size_t)(b * 8 + s) * 16 + v) * 8;
        #pragma unroll
        for (int i = 0; i < 8; i++) dst[i] = u[i];
    }

    // --- T matrix: 32 rows (threads 0..31), row j = bits x0..x4 ---
    if (t < 32) {
        const int j = t;
        const int x0 = j & 1, x1 = (j >> 1) & 1, x2 = (j >> 2) & 1;
        const int x3 = (j >> 3) & 1, x4 = (j >> 4) & 1;
        float v8[8], v8b[8];
        #pragma unroll
        for (int i = 0; i < 8; i++) v8[i] = 0.0f;
        #pragma unroll
        for (int i = 0; i < 4; i++) v8[i + 4 * x1] = sr01[(x1 * 2 + x0) * 4 + i];
        site_mv_T(sB + (2 - 2) * 20, x2, v8, v8b);
        site_mv_T(sB + (3 - 2) * 20, x3, v8b, v8);
        site_mv_T(sB + (4 - 2) * 20, x4, v8, v8b);
        float* dst = g_T + b * 256 + j * 8;
        #pragma unroll
        for (int i = 0; i < 8; i++) dst[i] = v8b[i];
    }
}

// ---------------------------------------------------------------------------
// Main kernel: grid (8, BATCH), 256 threads. Thread t = amp bits 5-12,
// blockIdx.x = bits 13-15. Loads U (sites 15..9 done), applies sites 8..5,
// then 32 amps via T-matrix dots. Output: packed float32 real parts.
// ---------------------------------------------------------------------------
__global__ void __launch_bounds__(256) mps_kernel(float* __restrict__ outf,
                                                  long long nfloat, int as_complex) {
    __shared__ float sT[256];
    __shared__ float sB[80];
    const int t = threadIdx.x;
    const int s = blockIdx.x;
    const int b = blockIdx.y;

    sT[t] = g_T[b * 256 + t];
    if (t < 80) sB[t] = g_B[b * 80 + t];
    __syncthreads();

    float u[8], u2[8];
    {
        const float4* Up = (const float4*)(g_U + ((size_t)(b * 8 + s) * 16 + (t >> 4)) * 8);
        float4 ua = __ldg(Up), ub = __ldg(Up + 1);
        u[0] = ua.x; u[1] = ua.y; u[2] = ua.z; u[3] = ua.w;
        u[4] = ub.x; u[5] = ub.y; u[6] = ub.z; u[7] = ub.w;
    }
    site_mv(sB + 3 * 20, (t >> 3) & 1, u, u2);  // site 8
    site_mv(sB + 2 * 20, (t >> 2) & 1, u2, u);  // site 7
    site_mv(sB + 1 * 20, (t >> 1) & 1, u, u2);  // site 6
    site_mv(sB + 0 * 20, t & 1, u2, u);         // site 5

    const long long slab = (long long)b * N_STATES + (long long)s * 8192 + (long long)t * 32;
    const float4* T4 = (const float4*)sT;

    if (!as_complex && slab + 32 <= nfloat) {
        #pragma unroll
        for (int g = 0; g < 8; g++) {
            float4 o;
            float* ov = (float*)&o;
            #pragma unroll
            for (int jj = 0; jj < 4; jj++) {
                const int j = g * 4 + jj;
                float4 r0 = T4[j * 2], r1 = T4[j * 2 + 1];
                float acc = r0.x * u[0];
                acc = fmaf(r0.y, u[1], acc);
                acc = fmaf(r0.z, u[2], acc);
                acc = fmaf(r0.w, u[3], acc);
                acc = fmaf(r1.x, u[4], acc);
                acc = fmaf(r1.y, u[5], acc);
                acc = fmaf(r1.z, u[6], acc);
                acc = fmaf(r1.w, u[7], acc);
                ov[jj] = acc;
            }
            ((float4*)(outf + slab))[g] = o;
        }
    } else {
        #pragma unroll
        for (int j = 0; j < 32; j++) {
            float4 r0 = T4[j * 2], r1 = T4[j * 2 + 1];
            float acc = r0.x * u[0];
            acc = fmaf(r0.y, u[1], acc);
            acc = fmaf(r0.z, u[2], acc);
            acc = fmaf(r0.w, u[3], acc);
            acc = fmaf(r1.x, u[4], acc);
            acc = fmaf(r1.y, u[5], acc);
            acc = fmaf(r1.z, u[6], acc);
            acc = fmaf(r1.w, u[7], acc);
            const long long idx = slab + j;
            if (as_complex) {
                if (2 * idx + 1 < nfloat) ((float2*)outf)[idx] = make_float2(acc, 0.0f);
            } else {
                if (idx < nfloat) outf[idx] = acc;
            }
        }
    }
}

// ---------------------------------------------------------------------------
extern "C" void kernel_launch(void* const* d_in, const int* in_sizes, int n_in,
                              void* d_out, int out_size) {
    // Bind inputs by element count (all distinct) -> immune to metadata order.
    const float *X = nullptr, *rot = nullptr, *ent = nullptr;
    const float *W1 = nullptr, *b1 = nullptr, *W2 = nullptr, *b2 = nullptr;
    for (int i = 0; i < n_in; i++) {
        switch (in_sizes[i]) {
            case 25600: X   = (const float*)d_in[i]; break;
            case 144:   rot = (const float*)d_in[i]; break;
            case 45:    ent = (const float*)d_in[i]; break;
            case 6400:  W1  = (const float*)d_in[i]; break;
            case 64:    b1  = (const float*)d_in[i]; break;
            case 1024:  W2  = (const float*)d_in[i]; break;
            case 16:    b2  = (const float*)d_in[i]; break;
            default: break;
        }
    }
    if (!X || !rot || !ent || !W1 || !b1 || !W2 || !b2) return;

    const long long NCPLX = (long long)BATCH * N_STATES;  // 16777216
    long long nfloat = (long long)out_size;
    int as_complex = ((long long)out_size >= 2 * NCPLX) ? 1 : 0;
    float* outf = (float*)d_out;

    prep_kernel<<<BATCH, 128>>>(X, rot, ent, W1, b1, W2, b2);
    dim3 g(8, BATCH);
    mps_kernel<<<g, 256>>>(outf, nfloat, as_complex);
}

// round 12
// speedup vs baseline: 1.4312x; 1.4312x over previous
#include <cuda_runtime.h>
#include <cuda_bf16.h>
#include <math.h>

#define N_STATES 65536
#define BATCH 256

// Per-batch data computed by prep:
// g_B : sites 3..8 structured factors, 20 floats each: [b*120 + (q-3)*20 + i]
// g_T2: rows r01*P2^T(x2): [b*32 + j2*4 + i], j2 = x0+2x1+4x2
// g_U : bond vectors after sites 15..9: [(b*128 + w)*8 + k], w = x9..x15
__device__ float g_B[BATCH * 120];
__device__ float g_T2[BATCH * 32];
__device__ float g_U[BATCH * 128 * 8];

// float4-granular XOR swizzle for conflict-free smem staging
#define PHYS4(i) ((i) ^ (((i) >> 3) & 7))

// ---------------------------------------------------------------------------
// Structured site tensor: 20 floats B = {B1[4], B2[8], B3[8]}.
// Forward matvec: uo[l1+2l2+4l3] = sum_{r1,r2} B1[l1,r1] B2[l2,r2,r1] B3[l3,x,r2]
//                                   * u[r1+2r2+4x]
// ---------------------------------------------------------------------------
__device__ __forceinline__ void site_mv(const float* __restrict__ B, int x,
                                        const float* __restrict__ u,
                                        float* __restrict__ uo) {
    const float* B2 = B + 4;
    const float* B3 = B + 12;
    float va[8];
    #pragma unroll
    for (int l3 = 0; l3 < 2; l3++)
        #pragma unroll
        for (int r2 = 0; r2 < 2; r2++) {
            float c = B3[l3 * 4 + x * 2 + r2];
            #pragma unroll
            for (int r1 = 0; r1 < 2; r1++)
                va[l3 * 4 + r2 * 2 + r1] = c * u[r1 + 2 * r2 + 4 * x];
        }
    float vb[8];
    #pragma unroll
    for (int l3 = 0; l3 < 2; l3++)
        #pragma unroll
        for (int l2 = 0; l2 < 2; l2++)
            #pragma unroll
            for (int r1 = 0; r1 < 2; r1++)
                vb[l3 * 4 + l2 * 2 + r1] =
                    fmaf(B2[l2 * 4 + 2 + r1], va[l3 * 4 + 2 + r1],
                         B2[l2 * 4 + 0 + r1] * va[l3 * 4 + 0 + r1]);
    #pragma unroll
    for (int l3 = 0; l3 < 2; l3++)
        #pragma unroll
        for (int l2 = 0; l2 < 2; l2++)
            #pragma unroll
            for (int l1 = 0; l1 < 2; l1++)
                uo[l1 + 2 * l2 + 4 * l3] =
                    fmaf(B[l1 * 2 + 1], vb[l3 * 4 + l2 * 2 + 1],
                         B[l1 * 2 + 0] * vb[l3 * 4 + l2 * 2 + 0]);
}

// Transposed apply (row vector): vo = v * P(x); nonzero only at slots 4x..4x+3.
__device__ __forceinline__ void site_mv_T(const float* __restrict__ B, int x,
                                          const float* __restrict__ v,
                                          float* __restrict__ vo) {
    const float* B2 = B + 4;
    const float* B3 = B + 12;
    float w[8];
    #pragma unroll
    for (int l3 = 0; l3 < 2; l3++)
        #pragma unroll
        for (int l2 = 0; l2 < 2; l2++)
            #pragma unroll
            for (int r1 = 0; r1 < 2; r1++)
                w[l3 * 4 + l2 * 2 + r1] =
                    fmaf(v[1 + 2 * l2 + 4 * l3], B[2 + r1],
                         v[0 + 2 * l2 + 4 * l3] * B[0 + r1]);
    float w2[8];
    #pragma unroll
    for (int l3 = 0; l3 < 2; l3++)
        #pragma unroll
        for (int r2 = 0; r2 < 2; r2++)
            #pragma unroll
            for (int r1 = 0; r1 < 2; r1++)
                w2[l3 * 4 + r2 * 2 + r1] =
                    fmaf(B2[4 + r2 * 2 + r1], w[l3 * 4 + 2 + r1],
                         B2[0 + r2 * 2 + r1] * w[l3 * 4 + 0 + r1]);
    #pragma unroll
    for (int r2 = 0; r2 < 2; r2++)
        #pragma unroll
        for (int r1 = 0; r1 < 2; r1++) {
            vo[r1 + 2 * r2 + 4 * x] =
                fmaf(B3[4 + x * 2 + r2], w2[4 + r2 * 2 + r1],
                     B3[0 + x * 2 + r2] * w2[0 + r2 * 2 + r1]);
            vo[r1 + 2 * r2 + 4 * (1 - x)] = 0.0f;
        }
}

// B-factor builder: B^{l=0} = M ; B^{l=1}[i,j] = (1-p) M[i,j] + p M[1-i,j]
__device__ __forceinline__ float bgf(const float* M, float p, int l, int i, int j) {
    float v = M[i * 2 + j];
    if (l) v = (1.0f - p) * v + p * M[(1 - i) * 2 + j];
    return v;
}

// ---------------------------------------------------------------------------
// Prep (grid BATCH, 128 thr): MLP -> gates -> site factors -> U(128), T2, B.
// ---------------------------------------------------------------------------
__global__ void prep_kernel(const float* __restrict__ X,
                            const float* __restrict__ rot,
                            const float* __restrict__ ent,
                            const float* __restrict__ W1,
                            const float* __restrict__ b1,
                            const float* __restrict__ W2,
                            const float* __restrict__ b2) {
    int b = blockIdx.x;
    int t = threadIdx.x;  // 128 threads
    __shared__ float sx[100];
    __shared__ float sh[64];
    __shared__ float shq[16];
    __shared__ float sM[3][16][4];
    __shared__ float sp[3][15];
    __shared__ float sB[13 * 20];   // sites 2..14: (q-2)*20
    __shared__ float sW15[16];
    __shared__ float sr01[16];

    if (t < 100) sx[t] = X[b * 100 + t];
    __syncthreads();

    if (t < 64) {
        float acc = b1[t];
        #pragma unroll 4
        for (int k = 0; k < 100; k++) acc = fmaf(sx[k], W1[k * 64 + t], acc);
        sh[t] = fmaxf(acc, 0.0f);
    }
    __syncthreads();

    if (t < 16) {
        float acc = b2[t];
        #pragma unroll
        for (int j = 0; j < 64; j++) acc = fmaf(sh[j], W2[j * 16 + t], acc);
        shq[t] = tanhf(acc);
    }
    __syncthreads();

    if (t < 48) {
        int layer = t / 16, q = t % 16;
        float hv = shq[q];
        float c[3], s[3];
        #pragma unroll
        for (int i = 0; i < 3; i++) {
            float ang = rot[(layer * 16 + q) * 3 + i] * hv;
            sincosf(0.5f * ang, &s[i], &c[i]);
        }
        sM[layer][q][0] =  c[0] * c[1] * c[2];
        sM[layer][q][1] = -s[0] * s[1] * s[2];
        sM[layer][q][2] =  s[0] * s[1] * c[2];
        sM[layer][q][3] =  c[0] * c[1] * s[2];
    }
    if (t >= 48 && t < 93) {
        int i = t - 48;
        sp[i / 15][i % 15] = 1.0f / (1.0f + expf(-ent[i]));
    }
    __syncthreads();

    if (t >= 2 && t <= 14) {
        int q = t;
        float* o = sB + (q - 2) * 20;
        float p1 = sp[0][q - 1], p2 = sp[1][q - 1], p3 = sp[2][q - 1];
        const float* M1 = sM[0][q];
        const float* M2 = sM[1][q];
        const float* M3 = sM[2][q];
        #pragma unroll
        for (int l = 0; l < 2; l++)
            #pragma unroll
            for (int r1 = 0; r1 < 2; r1++)
                o[l * 2 + r1] = bgf(M1, p1, l, r1, 0);
        #pragma unroll
        for (int l = 0; l < 2; l++)
            #pragma unroll
            for (int r2 = 0; r2 < 2; r2++)
                #pragma unroll
                for (int r1 = 0; r1 < 2; r1++)
                    o[4 + l * 4 + r2 * 2 + r1] = bgf(M2, p2, l, r2, r1);
        #pragma unroll
        for (int l = 0; l < 2; l++)
            #pragma unroll
            for (int x = 0; x < 2; x++)
                #pragma unroll
                for (int r2 = 0; r2 < 2; r2++)
                    o[12 + l * 4 + x * 2 + r2] = bgf(M3, p3, l, x, r2);
    }
    if (t == 15) {
        float p1 = sp[0][14], p2 = sp[1][14], p3 = sp[2][14];
        const float* M1 = sM[0][15];
        const float* M2 = sM[1][15];
        const float* M3 = sM[2][15];
        for (int x = 0; x < 2; x++)
            for (int l3 = 0; l3 < 2; l3++)
                for (int l2 = 0; l2 < 2; l2++)
                    for (int l1 = 0; l1 < 2; l1++) {
                        float acc = 0.0f;
                        for (int i = 0; i < 2; i++)
                            for (int j = 0; j < 2; j++)
                                acc += bgf(M3, p3, l3, x, i) *
                                       bgf(M2, p2, l2, i, j) *
                                       bgf(M1, p1, l1, j, 0);
                        sW15[x * 8 + (l1 + 2 * l2 + 4 * l3)] = acc;
                    }
    }
    if (t == 16) {
        float p1 = sp[0][0], p2 = sp[1][0], p3 = sp[2][0];
        const float* N1 = sM[0][0];
        const float* N2 = sM[1][0];
        const float* N3 = sM[2][0];
        const float* M1 = sM[0][1];
        const float* M2 = sM[1][1];
        const float* M3 = sM[2][1];
        for (int x1 = 0; x1 < 2; x1++)
            for (int x0 = 0; x0 < 2; x0++)
                for (int r2 = 0; r2 < 2; r2++)
                    for (int r1 = 0; r1 < 2; r1++) {
                        float acc = 0.0f;
                        for (int l1 = 0; l1 < 2; l1++)
                            for (int l2 = 0; l2 < 2; l2++)
                                acc += N1[l1 * 2] * N2[l2 * 2 + l1] * N3[x0 * 2 + l2]
                                     * bgf(M1, p1, l1, r1, 0)
                                     * bgf(M2, p2, l2, r2, r1)
                                     * bgf(M3, p3, x0, x1, r2);
                        sr01[(x1 * 2 + x0) * 4 + (r1 + 2 * r2)] = acc;
                    }
    }
    __syncthreads();

    // --- export site 3..8 factors (offsets 20..139 of sB) ---
    if (t < 120) g_B[b * 120 + t] = sB[20 + t];

    // --- U table: w = x9..x15, one per thread (128 threads) ---
    {
        const int w = t;
        float u[8], u2[8];
        const int x15 = (w >> 6) & 1;
        #pragma unroll
        for (int i = 0; i < 8; i++) u[i] = sW15[x15 * 8 + i];
        site_mv(sB + (14 - 2) * 20, (w >> 5) & 1, u, u2);
        site_mv(sB + (13 - 2) * 20, (w >> 4) & 1, u2, u);
        site_mv(sB + (12 - 2) * 20, (w >> 3) & 1, u, u2);
        site_mv(sB + (11 - 2) * 20, (w >> 2) & 1, u2, u);
        site_mv(sB + (10 - 2) * 20, (w >> 1) & 1, u, u2);
        site_mv(sB + (9 - 2) * 20, w & 1, u2, u);
        float* dst = g_U + ((size_t)(b * 128 + w)) * 8;
        #pragma unroll
        for (int i = 0; i < 8; i++) dst[i] = u[i];
    }

    // --- T2 rows: j2 = x0+2x1+4x2, 8 rows x 4 ---
    if (t < 8) {
        const int x0 = t & 1, x1 = (t >> 1) & 1, x2 = (t >> 2) & 1;
        float v8[8], v8b[8];
        #pragma unroll
        for (int i = 0; i < 8; i++) v8[i] = 0.0f;
        #pragma unroll
        for (int i = 0; i < 4; i++) v8[i + 4 * x1] = sr01[(x1 * 2 + x0) * 4 + i];
        site_mv_T(sB + (2 - 2) * 20, x2, v8, v8b);
        #pragma unroll
        for (int i = 0; i < 4; i++) g_T2[b * 32 + t * 4 + i] = v8b[i + 4 * x2];
    }
}

// ---------------------------------------------------------------------------
// Main kernel: grid (4, BATCH), 256 thr. t = amp bits 6-13, bx = bits 14-15.
// 64 amps/thread. U covers sites 15..9; apply sites 8..5 (x5 both), then
// sites 4,3 forward and T2 register dots for bits 0-2. Output staged in
// swizzled smem, written fully coalesced.
// ---------------------------------------------------------------------------
__global__ void __launch_bounds__(256) mps_kernel(float* __restrict__ outf,
                                                  long long nfloat, int as_complex) {
    __shared__ float4 stage[2048];   // 32KB
    __shared__ float sB[120];
    __shared__ float sT2[32];
    const int t = threadIdx.x;
    const int bx = blockIdx.x;
    const int b = blockIdx.y;

    if (t < 120) sB[t] = g_B[b * 120 + t];
    if (t >= 128 && t < 160) sT2[t - 128] = g_T2[b * 32 + (t - 128)];
    __syncthreads();

    float T2r[32];
    #pragma unroll
    for (int i = 0; i < 32; i++) T2r[i] = sT2[i];

    float u[8], u2[8];
    {
        const int w = (bx << 5) | (t >> 3);
        const float4* Up = (const float4*)(g_U + ((size_t)(b * 128 + w)) * 8);
        float4 ua = __ldg(Up), ub = __ldg(Up + 1);
        u[0] = ua.x; u[1] = ua.y; u[2] = ua.z; u[3] = ua.w;
        u[4] = ub.x; u[5] = ub.y; u[6] = ub.z; u[7] = ub.w;
    }
    site_mv(sB + 5 * 20, (t >> 2) & 1, u, u2);   // site 8
    site_mv(sB + 4 * 20, (t >> 1) & 1, u2, u);   // site 7
    site_mv(sB + 3 * 20, t & 1, u, u2);          // site 6
    float u5[2][8];
    site_mv(sB + 2 * 20, 0, u2, u5[0]);          // site 5, x5=0
    site_mv(sB + 2 * 20, 1, u2, u5[1]);          // site 5, x5=1

    const long long base4 = (long long)b * 16384 + (long long)bx * 4096;  // float4 units
    const bool fast = (!as_complex) &&
                      (4 * (base4 + 4096) <= nfloat);

    #pragma unroll
    for (int x5 = 0; x5 < 2; x5++) {
        #pragma unroll
        for (int x4 = 0; x4 < 2; x4++) {
            float u4[8];
            site_mv(sB + 1 * 20, x4, u5[x5], u4);   // site 4
            #pragma unroll
            for (int x3 = 0; x3 < 2; x3++) {
                float u3[8];
                site_mv(sB + 0 * 20, x3, u4, u3);   // site 3
                float4 vA, vB;
                // jlow 0..3 (x2=0): rows 0..3, slice u3[0..3]
                vA.x = fmaf(T2r[3],  u3[3], fmaf(T2r[2],  u3[2], fmaf(T2r[1],  u3[1], T2r[0]  * u3[0])));
                vA.y = fmaf(T2r[7],  u3[3], fmaf(T2r[6],  u3[2], fmaf(T2r[5],  u3[1], T2r[4]  * u3[0])));
                vA.z = fmaf(T2r[11], u3[3], fmaf(T2r[10], u3[2], fmaf(T2r[9],  u3[1], T2r[8]  * u3[0])));
                vA.w = fmaf(T2r[15], u3[3], fmaf(T2r[14], u3[2], fmaf(T2r[13], u3[1], T2r[12] * u3[0])));
                // jlow 4..7 (x2=1): rows 4..7, slice u3[4..7]
                vB.x = fmaf(T2r[19], u3[7], fmaf(T2r[18], u3[6], fmaf(T2r[17], u3[5], T2r[16] * u3[4])));
                vB.y = fmaf(T2r[23], u3[7], fmaf(T2r[22], u3[6], fmaf(T2r[21], u3[5], T2r[20] * u3[4])));
                vB.z = fmaf(T2r[27], u3[7], fmaf(T2r[26], u3[6], fmaf(T2r[25], u3[5], T2r[24] * u3[4])));
                vB.w = fmaf(T2r[31], u3[7], fmaf(T2r[30], u3[6], fmaf(T2r[29], u3[5], T2r[28] * u3[4])));
                const int c = x4 * 4 + x3 * 2;
                const int i4 = t * 8 + c;
                stage[PHYS4(i4)]     = vA;
                stage[PHYS4(i4 + 1)] = vB;
            }
        }
        __syncthreads();
        if (fast) {
            #pragma unroll
            for (int g = 0; g < 8; g++) {
                const int v = t + 256 * g;
                float4 val = stage[PHYS4(v)];
                const long long dst4 = base4 + (long long)(v >> 3) * 16 + x5 * 8 + (v & 7);
                ((float4*)outf)[dst4] = val;
            }
        } else {
            #pragma unroll
            for (int g = 0; g < 8; g++) {
                const int v = t + 256 * g;
                float4 val = stage[PHYS4(v)];
                const float* vv = (const float*)&val;
                const long long dst4 = base4 + (long long)(v >> 3) * 16 + x5 * 8 + (v & 7);
                #pragma unroll
                for (int k = 0; k < 4; k++) {
                    const long long A = 4 * dst4 + k;
                    if (as_complex) {
                        if (2 * A + 1 < nfloat)
                            ((float2*)outf)[A] = make_float2(vv[k], 0.0f);
                    } else {
                        if (A < nfloat) outf[A] = vv[k];
                    }
                }
            }
        }
        __syncthreads();
    }
}

// ---------------------------------------------------------------------------
extern "C" void kernel_launch(void* const* d_in, const int* in_sizes, int n_in,
                              void* d_out, int out_size) {
    // Bind inputs by element count (all distinct) -> immune to metadata order.
    const float *X = nullptr, *rot = nullptr, *ent = nullptr;
    const float *W1 = nullptr, *b1 = nullptr, *W2 = nullptr, *b2 = nullptr;
    for (int i = 0; i < n_in; i++) {
        switch (in_sizes[i]) {
            case 25600: X   = (const float*)d_in[i]; break;
            case 144:   rot = (const float*)d_in[i]; break;
            case 45:    ent = (const float*)d_in[i]; break;
            case 6400:  W1  = (const float*)d_in[i]; break;
            case 64:    b1  = (const float*)d_in[i]; break;
            case 1024:  W2  = (const float*)d_in[i]; break;
            case 16:    b2  = (const float*)d_in[i]; break;
            default: break;
        }
    }
    if (!X || !rot || !ent || !W1 || !b1 || !W2 || !b2) return;

    const long long NCPLX = (long long)BATCH * N_STATES;  // 16777216
    long long nfloat = (long long)out_size;
    int as_complex = ((long long)out_size >= 2 * NCPLX) ? 1 : 0;
    float* outf = (float*)d_out;

    prep_kernel<<<BATCH, 128>>>(X, rot, ent, W1, b1, W2, b2);
    dim3 g(4, BATCH);
    mps_kernel<<<g, 256>>>(outf, nfloat, as_complex);
}